// round 1
// baseline (speedup 1.0000x reference)
#include <cuda_runtime.h>

// Advect stencil, axis=1.
// rho, v: (16, 4100, 1024) f32 ; out: (16, 4096, 1024) f32
// out[b,k,c] = net(k) - net(k+1) with
//   net(i) = fp(i) + fm(i)
//   fp(i)  = (i==0      || v[i+1] <= 0) ? 0 : F[i+1] + hs(i+1)
//   fm(i)  = (i==4096   || v[i+2] >= 0) ? 0 : F[i+2] - hs(i+2)
//   hs(j)  = 0.5 * minmod(2(F[j]-F[j-1]), 0.5(F[j+1]-F[j-1]), 2(F[j+1]-F[j]))
//   F[j]   = rho[j]*v[j]

#define NB   16
#define NJ   4100
#define NC   1024
#define C4   (NC / 4)     // 256 float4 per row
#define NOUT 4096
#define TILE 64           // outputs per thread along j

__device__ __forceinline__ float4 f4mul(float4 a, float4 b) {
    return make_float4(a.x * b.x, a.y * b.y, a.z * b.z, a.w * b.w);
}

__device__ __forceinline__ float hs1(float fm1, float f0, float fp1) {
    float s0 = 2.0f * (f0 - fm1);
    float s1 = 0.5f * (fp1 - fm1);
    float s2 = 2.0f * (fp1 - f0);
    float mn = fminf(fminf(s0, s1), s2);
    float mx = fmaxf(fmaxf(s0, s1), s2);
    float r  = (mn < 0.0f) ? fminf(mx, 0.0f) : mn;
    return 0.5f * r;
}

__device__ __forceinline__ float4 hs4(float4 a, float4 b, float4 c) {
    return make_float4(hs1(a.x, b.x, c.x), hs1(a.y, b.y, c.y),
                       hs1(a.z, b.z, c.z), hs1(a.w, b.w, c.w));
}

// net(i) for one lane: fp part from (Fp, vp, hsp) = (F[i+1], v[i+1], hs(i+1)),
// fm part from (Fm, vm, hsm) = (F[i+2], v[i+2], hs(i+2)).
__device__ __forceinline__ float net1(float Fp, float vp, float hsp,
                                      float Fm, float vm, float hsm,
                                      bool fp_zero, bool fm_zero) {
    float fp = (!fp_zero && vp > 0.0f) ? (Fp + hsp) : 0.0f;
    float fm = (!fm_zero && vm < 0.0f) ? (Fm - hsm) : 0.0f;
    return fp + fm;
}

__device__ __forceinline__ float4 net4(float4 Fp, float4 vp, float4 hsp,
                                       float4 Fm, float4 vm, float4 hsm,
                                       bool fp_zero, bool fm_zero) {
    return make_float4(
        net1(Fp.x, vp.x, hsp.x, Fm.x, vm.x, hsm.x, fp_zero, fm_zero),
        net1(Fp.y, vp.y, hsp.y, Fm.y, vm.y, hsm.y, fp_zero, fm_zero),
        net1(Fp.z, vp.z, hsp.z, Fm.z, vm.z, hsm.z, fp_zero, fm_zero),
        net1(Fp.w, vp.w, hsp.w, Fm.w, vm.w, hsm.w, fp_zero, fm_zero));
}

__global__ void __launch_bounds__(256)
advect_kernel(const float4* __restrict__ rho,
              const float4* __restrict__ v,
              float4* __restrict__ out) {
    const int lane = threadIdx.x;            // float4 column 0..255
    const int k0   = blockIdx.x * TILE;      // first output index along j
    const int b    = blockIdx.y;

    const float4* rp = rho + (size_t)b * NJ * C4 + lane;
    const float4* vp = v   + (size_t)b * NJ * C4 + lane;
    float4*       op = out + (size_t)b * NOUT * C4 + (size_t)k0 * C4 + lane;

    // Preload j = k0 .. k0+3
    float4 r0 = rp[(size_t)(k0 + 0) * C4];
    float4 r1 = rp[(size_t)(k0 + 1) * C4];
    float4 r2 = rp[(size_t)(k0 + 2) * C4];
    float4 r3 = rp[(size_t)(k0 + 3) * C4];
    float4 w0 = vp[(size_t)(k0 + 0) * C4];
    float4 w1 = vp[(size_t)(k0 + 1) * C4];
    float4 w2 = vp[(size_t)(k0 + 2) * C4];
    float4 w3 = vp[(size_t)(k0 + 3) * C4];

    float4 F0 = f4mul(r0, w0);   // F[k0]
    float4 Fa = f4mul(r1, w1);   // F[k0+1]
    float4 Fb = f4mul(r2, w2);   // F[k0+2]
    float4 Fc = f4mul(r3, w3);   // F[k0+3]

    float4 hsa = hs4(F0, Fa, Fb);   // hs(k0+1)
    float4 hsb = hs4(Fa, Fb, Fc);   // hs(k0+2)

    // net(k0): fp from (F[k0+1], v[k0+1], hs(k0+1)); fm from (F[k0+2], v[k0+2], hs(k0+2))
    float4 net_prev = net4(Fa, w1, hsa, Fb, w2, hsb, /*fp_zero=*/(k0 == 0), /*fm_zero=*/false);

    // Rolling state for iteration k: Fb=F[k+2], Fc=F[k+3], vb=v[k+2], vc=v[k+3], hsb=hs(k+2)
    float4 vb = w2, vc = w3;

#pragma unroll 4
    for (int t = 0; t < TILE; ++t) {
        const int k = k0 + t;
        float4 rd = rp[(size_t)(k + 4) * C4];
        float4 wd = vp[(size_t)(k + 4) * C4];
        float4 Fd = f4mul(rd, wd);                 // F[k+4]
        float4 hsc = hs4(Fb, Fc, Fd);              // hs(k+3)

        // net(k+1): fp from (F[k+2], v[k+2], hs(k+2)); fm from (F[k+3], v[k+3], hs(k+3))
        const bool fm_zero = (k == NOUT - 1);      // i = k+1 == 4096
        float4 net_cur = net4(Fb, vb, hsb, Fc, vc, hsc, /*fp_zero=*/false, fm_zero);

        op[(size_t)t * C4] = make_float4(net_prev.x - net_cur.x,
                                         net_prev.y - net_cur.y,
                                         net_prev.z - net_cur.z,
                                         net_prev.w - net_cur.w);

        net_prev = net_cur;
        Fb = Fc; Fc = Fd;
        vb = vc; vc = wd;
        hsb = hsc;
    }
}

extern "C" void kernel_launch(void* const* d_in, const int* in_sizes, int n_in,
                              void* d_out, int out_size) {
    const float4* rho = (const float4*)d_in[0];
    const float4* v   = (const float4*)d_in[1];
    // d_in[2] is the 'axis' scalar (always 1 here) — ignored.
    float4* out = (float4*)d_out;

    dim3 grid(NOUT / TILE, NB);   // (64, 16)
    advect_kernel<<<grid, 256>>>(rho, v, out);
}